// round 5
// baseline (speedup 1.0000x reference)
#include <cuda_runtime.h>
#include <cuda_fp16.h>
#include <cstdint>

// Problem constants
#define N_TOK   4096
#define C_BOOKS 128
#define K_CENT  16
#define V_LEN   16
#define IN_DIM  2048
#define OUT_DIM 4096
#define KTOT    2048                   // 128 books * 16 centroids (one-hot K)

// Scratch (allocation-free rule: device globals)
__device__ unsigned char g_idxT[(size_t)C_BOOKS * N_TOK];   // [c][token]
__device__ __half g_Bt[(size_t)OUT_DIM * KTOT];             // [o][k] k-contiguous, 16 MB

// ---------------------------------------------------------------------------
__device__ __forceinline__ uint32_t smem_u32(const void* p) {
    uint32_t a;
    asm("{ .reg .u64 t; cvta.to.shared.u64 t, %1; cvt.u32.u64 %0, t; }" : "=r"(a) : "l"(p));
    return a;
}
// one-hot half2: t==0 -> (1,0), t==1 -> (0,1), else (0,0)
__device__ __forceinline__ uint32_t oh(uint32_t t) {
    return t == 0u ? 0x3C00u : (t == 1u ? 0x3C000000u : 0u);
}

// ---------------------------------------------------------------------------
// Kernel A: nearest-centroid indices (Chebyshev), exact vs reference argmin.
// 256 blocks x 256 thr; block = 16 tokens. x staged coalesced into smem
// (pitch 516 floats); centroids via warp-uniform __ldg (L1 broadcast).
// ---------------------------------------------------------------------------
__global__ void __launch_bounds__(256) quant_idx_kernel(
    const float* __restrict__ x, const float* __restrict__ cents)
{
    __shared__ float s_x[16 * 516];              // 33 KB
    int tid  = threadIdx.x;
    int tok0 = blockIdx.x * 16;
    int t    = tid & 15;

    for (int g = 0; g < 4; ++g) {
        __syncthreads();                         // prev pass done with s_x
        // Stage x: 16 tokens x 512 floats (cols g*512 ..), fully coalesced
        for (int i = tid; i < 16 * 128; i += 256) {
            int tt = i >> 7, j = i & 127;
            float4 v = *(const float4*)(x + (size_t)(tok0 + tt) * IN_DIM + g * 512 + j * 4);
            *(float4*)&s_x[tt * 516 + j * 4] = v;
        }
        __syncthreads();
#pragma unroll
        for (int p = 0; p < 2; ++p) {
            int bl = (tid >> 4) + p * 16;        // 0..31 book-in-group
            int c  = g * 32 + bl;
            float xv[16];
            const float4* xs = (const float4*)&s_x[t * 516 + bl * 16];
#pragma unroll
            for (int q = 0; q < 4; ++q) {
                float4 v = xs[q];
                xv[q*4+0] = v.x; xv[q*4+1] = v.y; xv[q*4+2] = v.z; xv[q*4+3] = v.w;
            }
            const float4* cb = (const float4*)(cents + (size_t)c * 256);
            float best = 3.4028235e38f; int bi = 0;
#pragma unroll
            for (int k = 0; k < K_CENT; ++k) {
                float d = 0.0f;
#pragma unroll
                for (int q = 0; q < 4; ++q) {
                    float4 cv = __ldg(cb + k * 4 + q);
                    d = fmaxf(d, fabsf(xv[q*4+0] - cv.x));
                    d = fmaxf(d, fabsf(xv[q*4+1] - cv.y));
                    d = fmaxf(d, fabsf(xv[q*4+2] - cv.z));
                    d = fmaxf(d, fabsf(xv[q*4+3] - cv.w));
                }
                if (d < best) { best = d; bi = k; }   // strict < == first min (argmin)
            }
            g_idxT[(size_t)c * N_TOK + tok0 + t] = (unsigned char)bi;
        }
    }
}

// ---------------------------------------------------------------------------
// Kernel B: LUT -> fp16 B^T.  g_Bt[o][c*16+k] = fp16( sum_v cents[c,k,v]*W[c*16+v,o] )
// ---------------------------------------------------------------------------
__global__ void __launch_bounds__(256) build_B_kernel(
    const float* __restrict__ wgt, const float* __restrict__ cents)
{
    __shared__ float sc[K_CENT * V_LEN];
    int c = blockIdx.x;
    int o = blockIdx.y * 256 + threadIdx.x;
    sc[threadIdx.x] = cents[(size_t)c * 256 + threadIdx.x];
    __syncthreads();

    float acc[K_CENT];
#pragma unroll
    for (int k = 0; k < K_CENT; ++k) acc[k] = 0.0f;
#pragma unroll
    for (int v = 0; v < V_LEN; ++v) {
        float wv = wgt[(size_t)(c * V_LEN + v) * OUT_DIM + o];
#pragma unroll
        for (int k = 0; k < K_CENT; ++k)
            acc[k] = fmaf(sc[k * V_LEN + v], wv, acc[k]);
    }
    __half2 h[8];
#pragma unroll
    for (int j = 0; j < 8; ++j)
        h[j] = __floats2half2_rn(acc[2 * j], acc[2 * j + 1]);
    uint4* dst = (uint4*)(g_Bt + (size_t)o * KTOT + c * 16);
    dst[0] = *(uint4*)&h[0];
    dst[1] = *(uint4*)&h[4];
}

// ---------------------------------------------------------------------------
// Kernel C: one-hot GEMM via mma.sync m16n8k16. CTA 256 tok x 128 out,
// 512 thr (16 warps, warp tile 32x64). 3-stage cp.async (1 sync/iter),
// ldmatrix.x4, A synthesized from idx bytes.
// ---------------------------------------------------------------------------
#define SM_IDX  0                       // 128 books x 256 tokens = 32 KB
#define BSTG    (128 * 144)             // 18432 B per stage
#define SM_B    32768
#define SM_BIAS (SM_B + 3 * BSTG)       // 88064
#define SM_TOT  (SM_BIAS + 512)         // 88576

#define MMA(d, a0, a1, a2, a3, b0, b1) \
    asm volatile("mma.sync.aligned.m16n8k16.row.col.f32.f16.f16.f32 " \
        "{%0,%1,%2,%3}, {%4,%5,%6,%7}, {%8,%9}, {%0,%1,%2,%3};" \
        : "+f"((d)[0]), "+f"((d)[1]), "+f"((d)[2]), "+f"((d)[3]) \
        : "r"(a0), "r"(a1), "r"(a2), "r"(a3), "r"(b0), "r"(b1))

__global__ void __launch_bounds__(512, 1) onehot_hmma_kernel(
    const float* __restrict__ bias, float* __restrict__ out)
{
    extern __shared__ __align__(128) unsigned char smem[];
    const uint32_t sb = smem_u32(smem);
    const int tid = threadIdx.x, lane = tid & 31, w = tid >> 5;
    const int ms = w & 7, ns = w >> 3;          // 8 m-strips x 2 n-strips
    const int m0 = blockIdx.y * 256, o0 = blockIdx.x * 128;

    // Stage idx (128 books x 256 tokens) + bias
    {
        uint4* si = (uint4*)(smem + SM_IDX);
        for (int i = tid; i < 2048; i += 512)
            si[i] = *(const uint4*)(g_idxT + ((size_t)(i >> 4) << 12) + m0 + (i & 15) * 16);
        float* sbias = (float*)(smem + SM_BIAS);
        if (tid < 128) sbias[tid] = bias[o0 + tid];
    }

    const __half* gB = g_Bt + (size_t)o0 * KTOT;

    // Prologue: stages 0, 1
#pragma unroll
    for (int s = 0; s < 2; ++s) {
        uint32_t dst = sb + SM_B + s * BSTG;
        const __half* src = gB + s * 64;
#pragma unroll
        for (int r = 0; r < 2; ++r) {
            int i = tid + r * 512, n = i >> 3, ch = i & 7;
            asm volatile("cp.async.cg.shared.global [%0], [%1], 16;"
                :: "r"(dst + n * 144 + ch * 16), "l"(src + (size_t)n * KTOT + ch * 8));
        }
        asm volatile("cp.async.commit_group;" ::: "memory");
    }

    float acc[2][8][4];
#pragma unroll
    for (int mf = 0; mf < 2; ++mf)
#pragma unroll
        for (int nf = 0; nf < 8; ++nf)
#pragma unroll
            for (int q = 0; q < 4; ++q) acc[mf][nf][q] = 0.0f;

    const uint32_t c0   = (uint32_t)((lane & 3) * 2);
    // ldmatrix.x4 lane address: rows n = (lane>>4)*8 + (lane&7), k-half = (lane>>3)&1
    const uint32_t lmb  = (uint32_t)((((lane >> 4) * 8 + (lane & 7)) * 144) + ((lane >> 3) & 1) * 16);
    const unsigned char* s_idx = smem + SM_IDX;
    const int rbase = ms * 32 + (lane >> 2);

    for (int s = 0; s < 32; ++s) {
        asm volatile("cp.async.wait_group 1;" ::: "memory");
        __syncthreads();
        // Issue stage s+2 into buffer (s+2)%3 (freed: consumed at iter s-1)
        if (s + 2 < 32) {
            uint32_t dst = sb + SM_B + ((s + 2) % 3) * BSTG;
            const __half* src = gB + (s + 2) * 64;
#pragma unroll
            for (int r = 0; r < 2; ++r) {
                int i = tid + r * 512, n = i >> 3, ch = i & 7;
                asm volatile("cp.async.cg.shared.global [%0], [%1], 16;"
                    :: "r"(dst + n * 144 + ch * 16), "l"(src + (size_t)n * KTOT + ch * 8));
            }
        }
        asm volatile("cp.async.commit_group;" ::: "memory");

        uint32_t bufB = sb + SM_B + (s % 3) * BSTG;
#pragma unroll
        for (int cb = 0; cb < 4; ++cb) {
            int c = s * 4 + cb;
            const unsigned char* ip = s_idx + (c << 8) + rbase;
            uint32_t i0 = ip[0], i1 = ip[8], i2 = ip[16], i3 = ip[24];
            uint32_t t0 = i0 ^ c0, t1 = i1 ^ c0, t2 = i2 ^ c0, t3 = i3 ^ c0;
            uint32_t a00 = oh(t0),     a01 = oh(t1);
            uint32_t a02 = oh(t0 ^ 8), a03 = oh(t1 ^ 8);
            uint32_t a10 = oh(t2),     a11 = oh(t3);
            uint32_t a12 = oh(t2 ^ 8), a13 = oh(t3 ^ 8);
            uint32_t kb = bufB + (uint32_t)(cb * 32) + (uint32_t)(ns * 64 * 144) + lmb;
#pragma unroll
            for (int nfp = 0; nfp < 4; ++nfp) {
                uint32_t b0, b1, b2, b3;
                asm volatile("ldmatrix.sync.aligned.m8n8.x4.shared.b16 {%0,%1,%2,%3}, [%4];"
                             : "=r"(b0), "=r"(b1), "=r"(b2), "=r"(b3)
                             : "r"(kb + (uint32_t)(nfp * 16 * 144)));
                MMA(acc[0][2*nfp],   a00, a01, a02, a03, b0, b1);
                MMA(acc[1][2*nfp],   a10, a11, a12, a13, b0, b1);
                MMA(acc[0][2*nfp+1], a00, a01, a02, a03, b2, b3);
                MMA(acc[1][2*nfp+1], a10, a11, a12, a13, b2, b3);
            }
        }
    }

    // Epilogue: add bias, store
    const float* sbias = (const float*)(smem + SM_BIAS);
#pragma unroll
    for (int mf = 0; mf < 2; ++mf) {
        int row = m0 + ms * 32 + mf * 16 + (lane >> 2);
#pragma unroll
        for (int nf = 0; nf < 8; ++nf) {
            int colL = ns * 64 + nf * 8 + (int)c0;
            float2 bv = *(const float2*)(sbias + colL);
            float2 v0 = make_float2(acc[mf][nf][0] + bv.x, acc[mf][nf][1] + bv.y);
            float2 v1 = make_float2(acc[mf][nf][2] + bv.x, acc[mf][nf][3] + bv.y);
            *(float2*)(out + (size_t)row * OUT_DIM + o0 + colL) = v0;
            *(float2*)(out + (size_t)(row + 8) * OUT_DIM + o0 + colL) = v1;
        }
    }
}

// ---------------------------------------------------------------------------
extern "C" void kernel_launch(void* const* d_in, const int* in_sizes, int n_in,
                              void* d_out, int out_size)
{
    const float* x     = (const float*)d_in[0];
    const float* wgt   = (const float*)d_in[1];
    const float* cents = (const float*)d_in[2];
    const float* bias  = (const float*)d_in[3];
    float*       out   = (float*)d_out;

    cudaFuncSetAttribute(onehot_hmma_kernel,
                         cudaFuncAttributeMaxDynamicSharedMemorySize, SM_TOT);

    quant_idx_kernel<<<N_TOK / 16, 256>>>(x, cents);
    build_B_kernel<<<dim3(C_BOOKS, OUT_DIM / 256), 256>>>(wgt, cents);
    onehot_hmma_kernel<<<dim3(OUT_DIM / 128, N_TOK / 256), 512, SM_TOT>>>(bias, out);
}

// round 6
// speedup vs baseline: 1.1559x; 1.1559x over previous
#include <cuda_runtime.h>
#include <cuda_fp16.h>
#include <cstdint>

// Problem constants
#define N_TOK   4096
#define C_BOOKS 128
#define K_CENT  16
#define V_LEN   16
#define IN_DIM  2048
#define OUT_DIM 4096
#define KTOT    2048                   // 128 books * 16 centroids (one-hot K)

// Scratch (allocation-free rule: device globals)
__device__ unsigned char g_idxT[(size_t)C_BOOKS * N_TOK];   // [c][token]
__device__ __half g_Bt[(size_t)OUT_DIM * KTOT];             // [o][k] k-contiguous, 16 MB

// ---------------------------------------------------------------------------
__device__ __forceinline__ uint32_t smem_u32(const void* p) {
    uint32_t a;
    asm("{ .reg .u64 t; cvta.to.shared.u64 t, %1; cvt.u32.u64 %0, t; }" : "=r"(a) : "l"(p));
    return a;
}
// one-hot half2: t==0 -> (1,0), t==1 -> (0,1), else (0,0)
__device__ __forceinline__ uint32_t oh(uint32_t t) {
    return t == 0u ? 0x3C00u : (t == 1u ? 0x3C000000u : 0u);
}

// ---------------------------------------------------------------------------
// Kernel A: nearest-centroid indices (Chebyshev), exact vs reference argmin.
// R2 configuration (26us known): grid (128 token-blocks, 4 book-groups).
// ---------------------------------------------------------------------------
__global__ void __launch_bounds__(256) quant_idx_kernel(
    const float* __restrict__ x, const float* __restrict__ cents)
{
    __shared__ float sc[32 * 256];
    int tid = threadIdx.x, lane = tid & 31, w = tid >> 5;
    int token = blockIdx.x * 32 + lane;
    int cbase = blockIdx.y * 32;

    for (int i = tid; i < 32 * 256; i += 256)
        sc[i] = cents[(size_t)cbase * 256 + i];
    __syncthreads();

    const float* xrow = x + (size_t)token * IN_DIM;
    for (int cl = w * 4; cl < w * 4 + 4; ++cl) {
        int c = cbase + cl;
        float xv[16];
        const float4* xp = (const float4*)(xrow + c * V_LEN);
#pragma unroll
        for (int q = 0; q < 4; ++q) {
            float4 t = xp[q];
            xv[q*4+0] = t.x; xv[q*4+1] = t.y; xv[q*4+2] = t.z; xv[q*4+3] = t.w;
        }
        const float4* cb = (const float4*)(sc + cl * 256);
        float best = 3.4028235e38f; int bi = 0;
#pragma unroll
        for (int k = 0; k < K_CENT; ++k) {
            float d = 0.0f;
#pragma unroll
            for (int q = 0; q < 4; ++q) {
                float4 t = cb[k * 4 + q];
                d = fmaxf(d, fabsf(xv[q*4+0] - t.x));
                d = fmaxf(d, fabsf(xv[q*4+1] - t.y));
                d = fmaxf(d, fabsf(xv[q*4+2] - t.z));
                d = fmaxf(d, fabsf(xv[q*4+3] - t.w));
            }
            if (d < best) { best = d; bi = k; }   // strict < == first min (argmin)
        }
        g_idxT[(size_t)c * N_TOK + token] = (unsigned char)bi;
    }
}

// ---------------------------------------------------------------------------
// Kernel B: LUT -> fp16 B^T.  g_Bt[o][c*16+k] = fp16( sum_v cents[c,k,v]*W[c*16+v,o] )
// ---------------------------------------------------------------------------
__global__ void __launch_bounds__(256) build_B_kernel(
    const float* __restrict__ wgt, const float* __restrict__ cents)
{
    __shared__ float sc[K_CENT * V_LEN];
    int c = blockIdx.x;
    int o = blockIdx.y * 256 + threadIdx.x;
    sc[threadIdx.x] = cents[(size_t)c * 256 + threadIdx.x];
    __syncthreads();

    float acc[K_CENT];
#pragma unroll
    for (int k = 0; k < K_CENT; ++k) acc[k] = 0.0f;
#pragma unroll
    for (int v = 0; v < V_LEN; ++v) {
        float wv = wgt[(size_t)(c * V_LEN + v) * OUT_DIM + o];
#pragma unroll
        for (int k = 0; k < K_CENT; ++k)
            acc[k] = fmaf(sc[k * V_LEN + v], wv, acc[k]);
    }
    __half2 h[8];
#pragma unroll
    for (int j = 0; j < 8; ++j)
        h[j] = __floats2half2_rn(acc[2 * j], acc[2 * j + 1]);
    uint4* dst = (uint4*)(g_Bt + (size_t)o * KTOT + c * 16);
    dst[0] = *(uint4*)&h[0];
    dst[1] = *(uint4*)&h[4];
}

// ---------------------------------------------------------------------------
// Kernel C: one-hot GEMM via mma.sync m16n8k16. CTA 128 tok x 128 out,
// 256 thr (8 warps, warp tile 32x64), 2 CTAs/SM. 3-stage cp.async with a
// single __syncthreads per k-chunk; ldmatrix.x4; A synthesized from idx.
// ---------------------------------------------------------------------------
#define SM_IDX  0                       // 128 books x 128 tokens = 16 KB
#define BSTG    (128 * 144)             // 18432 B per stage
#define SM_B    16384
#define SM_BIAS (SM_B + 3 * BSTG)       // 71680
#define SM_TOT  (SM_BIAS + 512)         // 72192

#define MMA(d, a0, a1, a2, a3, b0, b1) \
    asm volatile("mma.sync.aligned.m16n8k16.row.col.f32.f16.f16.f32 " \
        "{%0,%1,%2,%3}, {%4,%5,%6,%7}, {%8,%9}, {%0,%1,%2,%3};" \
        : "+f"((d)[0]), "+f"((d)[1]), "+f"((d)[2]), "+f"((d)[3]) \
        : "r"(a0), "r"(a1), "r"(a2), "r"(a3), "r"(b0), "r"(b1))

__global__ void __launch_bounds__(256, 2) onehot_hmma_kernel(
    const float* __restrict__ bias, float* __restrict__ out)
{
    extern __shared__ __align__(128) unsigned char smem[];
    const uint32_t sb = smem_u32(smem);
    const int tid = threadIdx.x, lane = tid & 31, w = tid >> 5;
    const int ms = w & 3, ns = w >> 2;          // 4 m-strips x 2 n-strips
    const int m0 = blockIdx.y * 128, o0 = blockIdx.x * 128;

    // Stage idx (128 books x 128 tokens) + bias
    {
        uint4* si = (uint4*)(smem + SM_IDX);
        for (int i = tid; i < 1024; i += 256)
            si[i] = *(const uint4*)(g_idxT + ((size_t)(i >> 3) << 12) + m0 + (i & 7) * 16);
        float* sbias = (float*)(smem + SM_BIAS);
        if (tid < 128) sbias[tid] = bias[o0 + tid];
    }

    const __half* gB = g_Bt + (size_t)o0 * KTOT;

    // Prologue: stages 0, 1
#pragma unroll
    for (int s = 0; s < 2; ++s) {
        uint32_t dst = sb + SM_B + s * BSTG;
        const __half* src = gB + s * 64;
#pragma unroll
        for (int r = 0; r < 4; ++r) {
            int i = tid + r * 256, n = i >> 3, ch = i & 7;
            asm volatile("cp.async.cg.shared.global [%0], [%1], 16;"
                :: "r"(dst + n * 144 + ch * 16), "l"(src + (size_t)n * KTOT + ch * 8));
        }
        asm volatile("cp.async.commit_group;" ::: "memory");
    }

    float acc[2][8][4];
#pragma unroll
    for (int mf = 0; mf < 2; ++mf)
#pragma unroll
        for (int nf = 0; nf < 8; ++nf)
#pragma unroll
            for (int q = 0; q < 4; ++q) acc[mf][nf][q] = 0.0f;

    const uint32_t c0  = (uint32_t)((lane & 3) * 2);
    // ldmatrix.x4: lanes 0-7 -> n0-7/k0, 8-15 -> n0-7/k1, 16-23 -> n8-15/k0, 24-31 -> n8-15/k1
    const uint32_t lmb = (uint32_t)((((lane >> 4) * 8 + (lane & 7)) * 144) + ((lane >> 3) & 1) * 16);
    const unsigned char* s_idx = smem + SM_IDX;
    const int rbase = ms * 32 + (lane >> 2);

    for (int s = 0; s < 32; ++s) {
        asm volatile("cp.async.wait_group 1;" ::: "memory");
        __syncthreads();
        // Issue stage s+2 into buffer (s+2)%3 (consumed at iter s-1; the sync
        // above orders all warps' reads of that buffer before this write).
        if (s + 2 < 32) {
            uint32_t dst = sb + SM_B + ((s + 2) % 3) * BSTG;
            const __half* src = gB + (s + 2) * 64;
#pragma unroll
            for (int r = 0; r < 4; ++r) {
                int i = tid + r * 256, n = i >> 3, ch = i & 7;
                asm volatile("cp.async.cg.shared.global [%0], [%1], 16;"
                    :: "r"(dst + n * 144 + ch * 16), "l"(src + (size_t)n * KTOT + ch * 8));
            }
        }
        asm volatile("cp.async.commit_group;" ::: "memory");

        uint32_t bufB = sb + SM_B + (s % 3) * BSTG;
#pragma unroll
        for (int cb = 0; cb < 4; ++cb) {
            int c = s * 4 + cb;
            const unsigned char* ip = s_idx + (c << 7) + rbase;
            uint32_t i0 = ip[0], i1 = ip[8], i2 = ip[16], i3 = ip[24];
            uint32_t t0 = i0 ^ c0, t1 = i1 ^ c0, t2 = i2 ^ c0, t3 = i3 ^ c0;
            uint32_t a00 = oh(t0),     a01 = oh(t1);
            uint32_t a02 = oh(t0 ^ 8), a03 = oh(t1 ^ 8);
            uint32_t a10 = oh(t2),     a11 = oh(t3);
            uint32_t a12 = oh(t2 ^ 8), a13 = oh(t3 ^ 8);
            uint32_t kb = bufB + (uint32_t)(cb * 32) + (uint32_t)(ns * 64 * 144) + lmb;
#pragma unroll
            for (int nfp = 0; nfp < 4; ++nfp) {
                uint32_t b0, b1, b2, b3;
                asm volatile("ldmatrix.sync.aligned.m8n8.x4.shared.b16 {%0,%1,%2,%3}, [%4];"
                             : "=r"(b0), "=r"(b1), "=r"(b2), "=r"(b3)
                             : "r"(kb + (uint32_t)(nfp * 16 * 144)));
                MMA(acc[0][2*nfp],   a00, a01, a02, a03, b0, b1);
                MMA(acc[1][2*nfp],   a10, a11, a12, a13, b0, b1);
                MMA(acc[0][2*nfp+1], a00, a01, a02, a03, b2, b3);
                MMA(acc[1][2*nfp+1], a10, a11, a12, a13, b2, b3);
            }
        }
    }

    // Epilogue: add bias, store
    const float* sbias = (const float*)(smem + SM_BIAS);
#pragma unroll
    for (int mf = 0; mf < 2; ++mf) {
        int row = m0 + ms * 32 + mf * 16 + (lane >> 2);
#pragma unroll
        for (int nf = 0; nf < 8; ++nf) {
            int colL = ns * 64 + nf * 8 + (int)c0;
            float2 bv = *(const float2*)(sbias + colL);
            float2 v0 = make_float2(acc[mf][nf][0] + bv.x, acc[mf][nf][1] + bv.y);
            float2 v1 = make_float2(acc[mf][nf][2] + bv.x, acc[mf][nf][3] + bv.y);
            *(float2*)(out + (size_t)row * OUT_DIM + o0 + colL) = v0;
            *(float2*)(out + (size_t)(row + 8) * OUT_DIM + o0 + colL) = v1;
        }
    }
}

// ---------------------------------------------------------------------------
extern "C" void kernel_launch(void* const* d_in, const int* in_sizes, int n_in,
                              void* d_out, int out_size)
{
    const float* x     = (const float*)d_in[0];
    const float* wgt   = (const float*)d_in[1];
    const float* cents = (const float*)d_in[2];
    const float* bias  = (const float*)d_in[3];
    float*       out   = (float*)d_out;

    cudaFuncSetAttribute(onehot_hmma_kernel,
                         cudaFuncAttributeMaxDynamicSharedMemorySize, SM_TOT);

    quant_idx_kernel<<<dim3(N_TOK / 32, 4), 256>>>(x, cents);
    build_B_kernel<<<dim3(C_BOOKS, OUT_DIM / 256), 256>>>(wgt, cents);
    onehot_hmma_kernel<<<dim3(OUT_DIM / 128, N_TOK / 128), 256, SM_TOT>>>(bias, out);
}